// round 1
// baseline (speedup 1.0000x reference)
#include <cuda_runtime.h>
#include <math.h>

#define BB 2
#define SS 1024
#define DDIM 512
#define HH 8
#define DH 64
#define FF 2048
#define MM (BB*SS)

// ---------------- scratch (no allocation allowed) ----------------
__device__ float g_xn[MM*DDIM];
__device__ float g_q [MM*DDIM];
__device__ float g_k [MM*DDIM];
__device__ float g_v [MM*DDIM];
__device__ float g_att[MM*DDIM];
__device__ float g_h [MM*DDIM];
__device__ float g_hn[MM*DDIM];
__device__ float g_f1[MM*FF];
__device__ float g_u [MM];
__device__ float g_lam[BB];
__device__ int   g_sp [BB];

// ---------------- lam / sparse flag ----------------
__global__ void lam_kernel(const float* __restrict__ u_prev){
    int b = threadIdx.x;
    if (b < BB){
        float lam = 10.0f * expf(-5.0f * u_prev[b]);
        g_lam[b] = lam;
        g_sp[b]  = (lam >= 1.0f) ? 1 : 0;
    }
}

// ---------------- LayerNorm: one block per row, 128 threads ----------------
__global__ void ln_kernel(const float* __restrict__ x, const float* __restrict__ g,
                          const float* __restrict__ be, float* __restrict__ y){
    int row = blockIdx.x;
    int t = threadIdx.x;                 // 0..127, 4 elems each
    const float* xr = x + (size_t)row * DDIM;
    float4 v = *(const float4*)(xr + t*4);
    float s  = v.x + v.y + v.z + v.w;
    float ss = v.x*v.x + v.y*v.y + v.z*v.z + v.w*v.w;
    #pragma unroll
    for (int o = 16; o; o >>= 1){
        s  += __shfl_xor_sync(0xffffffffu, s,  o);
        ss += __shfl_xor_sync(0xffffffffu, ss, o);
    }
    __shared__ float ps[4], pss[4];
    int w = t >> 5;
    if ((t & 31) == 0){ ps[w] = s; pss[w] = ss; }
    __syncthreads();
    s  = ps[0] + ps[1] + ps[2] + ps[3];
    ss = pss[0] + pss[1] + pss[2] + pss[3];
    float mean = s * (1.0f/DDIM);
    float var  = ss * (1.0f/DDIM) - mean*mean;
    float inv  = rsqrtf(var + 1e-5f);
    float4 gv = *(const float4*)(g  + t*4);
    float4 bv = *(const float4*)(be + t*4);
    float4 o;
    o.x = (v.x - mean)*inv*gv.x + bv.x;
    o.y = (v.y - mean)*inv*gv.y + bv.y;
    o.z = (v.z - mean)*inv*gv.z + bv.z;
    o.w = (v.w - mean)*inv*gv.w + bv.w;
    *(float4*)(y + (size_t)row * DDIM + t*4) = o;
}

// ---------------- generic SGEMM: C[M,N] = A[M,K] @ W[N,K]^T (+bias)(+res)(gelu) ----------------
// BM=128, BN=64, BK=16, 256 threads, 8x4 micro-tile
__device__ __forceinline__ float gelu_exact(float v){
    return 0.5f * v * (1.0f + erff(v * 0.70710678118654752f));
}

template<bool GELU, bool RES>
__global__ void gemm_kernel(const float* __restrict__ A, const float* __restrict__ W,
                            const float* __restrict__ bias, const float* __restrict__ res,
                            float* __restrict__ C, int Kn, int Nn){
    __shared__ float As[16*132];   // [kk][m] transposed, pad 4
    __shared__ float Ws[16*68];    // [kk][n] transposed, pad 4
    const int m0 = blockIdx.y * 128;
    const int n0 = blockIdx.x * 64;
    const int tid = threadIdx.x;
    const int ty = tid >> 4, tx = tid & 15;

    float acc[8][4];
    #pragma unroll
    for (int i = 0; i < 8; i++)
        #pragma unroll
        for (int j = 0; j < 4; j++) acc[i][j] = 0.0f;

    for (int kt = 0; kt < Kn; kt += 16){
        // load A tile (128x16)
        #pragma unroll
        for (int it = 0; it < 2; it++){
            int flat = tid + it*256;
            int r = flat >> 2, c4 = (flat & 3) << 2;
            float4 a = *(const float4*)(A + (size_t)(m0 + r)*Kn + kt + c4);
            As[(c4+0)*132 + r] = a.x;
            As[(c4+1)*132 + r] = a.y;
            As[(c4+2)*132 + r] = a.z;
            As[(c4+3)*132 + r] = a.w;
        }
        // load W tile (64x16)
        {
            int r = tid >> 2, c4 = (tid & 3) << 2;
            float4 w4 = *(const float4*)(W + (size_t)(n0 + r)*Kn + kt + c4);
            Ws[(c4+0)*68 + r] = w4.x;
            Ws[(c4+1)*68 + r] = w4.y;
            Ws[(c4+2)*68 + r] = w4.z;
            Ws[(c4+3)*68 + r] = w4.w;
        }
        __syncthreads();
        #pragma unroll
        for (int kk = 0; kk < 16; kk++){
            float4 a0 = *(const float4*)(As + kk*132 + ty*8);
            float4 a1 = *(const float4*)(As + kk*132 + ty*8 + 4);
            float4 b  = *(const float4*)(Ws + kk*68  + tx*4);
            float av[8] = {a0.x,a0.y,a0.z,a0.w,a1.x,a1.y,a1.z,a1.w};
            float bw[4] = {b.x,b.y,b.z,b.w};
            #pragma unroll
            for (int i = 0; i < 8; i++)
                #pragma unroll
                for (int j = 0; j < 4; j++)
                    acc[i][j] += av[i] * bw[j];
        }
        __syncthreads();
    }

    float4 bv = *(const float4*)(bias + n0 + tx*4);
    #pragma unroll
    for (int i = 0; i < 8; i++){
        int m = m0 + ty*8 + i;
        float4 o;
        o.x = acc[i][0] + bv.x;
        o.y = acc[i][1] + bv.y;
        o.z = acc[i][2] + bv.z;
        o.w = acc[i][3] + bv.w;
        if (RES){
            float4 rv = *(const float4*)(res + (size_t)m*Nn + n0 + tx*4);
            o.x += rv.x; o.y += rv.y; o.z += rv.z; o.w += rv.w;
        }
        if (GELU){
            o.x = gelu_exact(o.x); o.y = gelu_exact(o.y);
            o.z = gelu_exact(o.z); o.w = gelu_exact(o.w);
        }
        *(float4*)(C + (size_t)m*Nn + n0 + tx*4) = o;
    }
}

// ---------------- unified flash attention (dense bias OR sparse band) ----------------
// Tile: 64 queries x 64 keys, 256 threads, 4x4 micro per thread.
// smem (dynamic): Qt[64d][68q], Kt[64d][68k] (reused as P[64k][68q]), Vs[64k][68d]
#define APAD 68
__global__ void attn_kernel(const float* __restrict__ Q, const float* __restrict__ K,
                            const float* __restrict__ V, float* __restrict__ O){
    extern __shared__ float sm[];
    float* Qt = sm;
    float* Kt = sm + 64*APAD;
    float* Vs = sm + 2*64*APAD;

    const int bh = blockIdx.y;
    const int b = bh / HH, h = bh % HH;
    const int q0 = blockIdx.x * 64;
    const float lam = g_lam[b];
    const int sp = g_sp[b];
    const int tid = threadIdx.x;
    const int ty = tid >> 4, tx = tid & 15;

    // load Q tile transposed: Qt[d][q]
    #pragma unroll
    for (int it = 0; it < 4; it++){
        int flat = tid + it*256;
        int r = flat >> 4, c4 = (flat & 15) << 2;
        float4 v = *(const float4*)(Q + (size_t)(b*SS + q0 + r)*DDIM + h*DH + c4);
        Qt[(c4+0)*APAD + r] = v.x;
        Qt[(c4+1)*APAD + r] = v.y;
        Qt[(c4+2)*APAD + r] = v.z;
        Qt[(c4+3)*APAD + r] = v.w;
    }

    float acc[4][4];
    float mrow[4], lrow[4];
    #pragma unroll
    for (int i = 0; i < 4; i++){
        mrow[i] = -INFINITY; lrow[i] = 0.0f;
        #pragma unroll
        for (int j = 0; j < 4; j++) acc[i][j] = 0.0f;
    }

    int klo = 0, khi = SS/64;
    if (sp){
        int lo = q0 - 51; if (lo < 0) lo = 0;
        int hi = q0 + 114; if (hi > SS-1) hi = SS-1;
        klo = lo >> 6; khi = (hi >> 6) + 1;
    }

    for (int kb = klo; kb < khi; kb++){
        __syncthreads();   // protect Kt/Vs from previous iteration's readers
        #pragma unroll
        for (int it = 0; it < 4; it++){
            int flat = tid + it*256;
            int r = flat >> 4, c4 = (flat & 15) << 2;
            const float* kp = K + (size_t)(b*SS + kb*64 + r)*DDIM + h*DH + c4;
            float4 kv = *(const float4*)kp;
            Kt[(c4+0)*APAD + r] = kv.x;
            Kt[(c4+1)*APAD + r] = kv.y;
            Kt[(c4+2)*APAD + r] = kv.z;
            Kt[(c4+3)*APAD + r] = kv.w;
            float4 vv = *(const float4*)(V + (size_t)(b*SS + kb*64 + r)*DDIM + h*DH + c4);
            *(float4*)(Vs + r*APAD + c4) = vv;
        }
        __syncthreads();

        // scores S[q][k]
        float s[4][4];
        #pragma unroll
        for (int i = 0; i < 4; i++)
            #pragma unroll
            for (int j = 0; j < 4; j++) s[i][j] = 0.0f;
        #pragma unroll 8
        for (int kk = 0; kk < 64; kk++){
            float4 qa = *(const float4*)(Qt + kk*APAD + ty*4);
            float4 kv = *(const float4*)(Kt + kk*APAD + tx*4);
            float qv[4] = {qa.x,qa.y,qa.z,qa.w};
            float kw[4] = {kv.x,kv.y,kv.z,kv.w};
            #pragma unroll
            for (int i = 0; i < 4; i++)
                #pragma unroll
                for (int j = 0; j < 4; j++)
                    s[i][j] += qv[i] * kw[j];
        }

        // online softmax update
        float p[4][4];
        #pragma unroll
        for (int i = 0; i < 4; i++){
            int qg = q0 + ty*4 + i;
            float val[4]; bool vld[4];
            float rm = -INFINITY;
            #pragma unroll
            for (int j = 0; j < 4; j++){
                int kg = kb*64 + tx*4 + j;
                bool inb = (kg >= qg - 51) && (kg <= qg + 51);
                float vv = s[i][j] * 0.125f;          // 1/sqrt(64)
                if (sp){ vld[j] = inb; }
                else   { vld[j] = true; if (!inb) vv -= lam; }
                val[j] = vv;
                if (vld[j]) rm = fmaxf(rm, vv);
            }
            #pragma unroll
            for (int o = 8; o; o >>= 1)
                rm = fmaxf(rm, __shfl_xor_sync(0xffffffffu, rm, o));
            float mnew = fmaxf(mrow[i], rm);
            float sf = (mrow[i] == mnew) ? 1.0f : expf(mrow[i] - mnew);
            float rs = 0.0f;
            #pragma unroll
            for (int j = 0; j < 4; j++){
                p[i][j] = vld[j] ? expf(val[j] - mnew) : 0.0f;
                rs += p[i][j];
            }
            #pragma unroll
            for (int o = 8; o; o >>= 1)
                rs += __shfl_xor_sync(0xffffffffu, rs, o);
            lrow[i] = lrow[i] * sf + rs;
            mrow[i] = mnew;
            #pragma unroll
            for (int j = 0; j < 4; j++) acc[i][j] *= sf;
        }
        __syncthreads();                 // everyone done reading Kt as K
        // write P transposed over Kt: P[k][q]
        #pragma unroll
        for (int i = 0; i < 4; i++)
            #pragma unroll
            for (int j = 0; j < 4; j++)
                Kt[(tx*4+j)*APAD + (ty*4+i)] = p[i][j];
        __syncthreads();

        // acc += P^T V
        #pragma unroll 8
        for (int kk = 0; kk < 64; kk++){
            float4 pv = *(const float4*)(Kt + kk*APAD + ty*4);
            float4 vv = *(const float4*)(Vs + kk*APAD + tx*4);
            float pa[4] = {pv.x,pv.y,pv.z,pv.w};
            float vb[4] = {vv.x,vv.y,vv.z,vv.w};
            #pragma unroll
            for (int i = 0; i < 4; i++)
                #pragma unroll
                for (int j = 0; j < 4; j++)
                    acc[i][j] += pa[i] * vb[j];
        }
    }

    #pragma unroll
    for (int i = 0; i < 4; i++){
        float inv = 1.0f / lrow[i];
        float4 o;
        o.x = acc[i][0]*inv; o.y = acc[i][1]*inv;
        o.z = acc[i][2]*inv; o.w = acc[i][3]*inv;
        *(float4*)(O + (size_t)(b*SS + q0 + ty*4 + i)*DDIM + h*DH + tx*4) = o;
    }
}

// ---------------- per-row u, then per-batch mean ----------------
__global__ void u_row_kernel(const float* __restrict__ outp, const float* __restrict__ x){
    int row = blockIdx.x;
    int t = threadIdx.x;   // 128
    float4 ov = *(const float4*)(outp + (size_t)row*DDIM + t*4);
    float4 xv = *(const float4*)(x    + (size_t)row*DDIM + t*4);
    float dx = ov.x - xv.x, dy = ov.y - xv.y, dz = ov.z - xv.z, dw = ov.w - xv.w;
    float d2 = dx*dx + dy*dy + dz*dz + dw*dw;
    float x2 = xv.x*xv.x + xv.y*xv.y + xv.z*xv.z + xv.w*xv.w;
    #pragma unroll
    for (int o = 16; o; o >>= 1){
        d2 += __shfl_xor_sync(0xffffffffu, d2, o);
        x2 += __shfl_xor_sync(0xffffffffu, x2, o);
    }
    __shared__ float pd[4], px[4];
    int w = t >> 5;
    if ((t & 31) == 0){ pd[w] = d2; px[w] = x2; }
    __syncthreads();
    if (t == 0){
        d2 = pd[0]+pd[1]+pd[2]+pd[3];
        x2 = px[0]+px[1]+px[2]+px[3];
        g_u[row] = sqrtf(d2) / (sqrtf(x2) + 1e-8f);
    }
}

__global__ void u_mean_kernel(float* __restrict__ outp, int out_size){
    int b = blockIdx.x;
    int t = threadIdx.x;   // 256
    float s = 0.0f;
    for (int i = t; i < SS; i += 256) s += g_u[b*SS + i];
    #pragma unroll
    for (int o = 16; o; o >>= 1) s += __shfl_xor_sync(0xffffffffu, s, o);
    __shared__ float ps[8];
    int w = t >> 5;
    if ((t & 31) == 0) ps[w] = s;
    __syncthreads();
    if (t == 0){
        s = 0.0f;
        #pragma unroll
        for (int i = 0; i < 8; i++) s += ps[i];
        int idx = MM*DDIM + b;
        if (idx < out_size) outp[idx] = s * (1.0f/SS);
    }
}

// ---------------- launch ----------------
extern "C" void kernel_launch(void* const* d_in, const int* in_sizes, int n_in,
                              void* d_out, int out_size){
    const float* x      = (const float*)d_in[0];
    const float* u_prev = (const float*)d_in[1];
    const float* wq = (const float*)d_in[2];  const float* bq = (const float*)d_in[3];
    const float* wk = (const float*)d_in[4];  const float* bk = (const float*)d_in[5];
    const float* wv = (const float*)d_in[6];  const float* bv = (const float*)d_in[7];
    const float* wo = (const float*)d_in[8];  const float* bo = (const float*)d_in[9];
    const float* ln1g = (const float*)d_in[10]; const float* ln1b = (const float*)d_in[11];
    const float* ln2g = (const float*)d_in[12]; const float* ln2b = (const float*)d_in[13];
    const float* w1 = (const float*)d_in[14]; const float* b1 = (const float*)d_in[15];
    const float* w2 = (const float*)d_in[16]; const float* b2 = (const float*)d_in[17];
    float* outp = (float*)d_out;

    float *p_xn, *p_q, *p_k, *p_v, *p_att, *p_h, *p_hn, *p_f1;
    cudaGetSymbolAddress((void**)&p_xn,  g_xn);
    cudaGetSymbolAddress((void**)&p_q,   g_q);
    cudaGetSymbolAddress((void**)&p_k,   g_k);
    cudaGetSymbolAddress((void**)&p_v,   g_v);
    cudaGetSymbolAddress((void**)&p_att, g_att);
    cudaGetSymbolAddress((void**)&p_h,   g_h);
    cudaGetSymbolAddress((void**)&p_hn,  g_hn);
    cudaGetSymbolAddress((void**)&p_f1,  g_f1);

    const int attn_smem = 3 * 64 * APAD * 4;   // 52224 B
    cudaFuncSetAttribute(attn_kernel, cudaFuncAttributeMaxDynamicSharedMemorySize, attn_smem);

    lam_kernel<<<1, 32>>>(u_prev);
    ln_kernel<<<MM, 128>>>(x, ln1g, ln1b, p_xn);

    dim3 gp(DDIM/64, MM/128);                  // (8,16)
    gemm_kernel<false,false><<<gp, 256>>>(p_xn, wq, bq, nullptr, p_q, DDIM, DDIM);
    gemm_kernel<false,false><<<gp, 256>>>(p_xn, wk, bk, nullptr, p_k, DDIM, DDIM);
    gemm_kernel<false,false><<<gp, 256>>>(p_xn, wv, bv, nullptr, p_v, DDIM, DDIM);

    attn_kernel<<<dim3(SS/64, BB*HH), 256, attn_smem>>>(p_q, p_k, p_v, p_att);

    gemm_kernel<false,true><<<gp, 256>>>(p_att, wo, bo, x, p_h, DDIM, DDIM);

    ln_kernel<<<MM, 128>>>(p_h, ln2g, ln2b, p_hn);

    gemm_kernel<true,false><<<dim3(FF/64, MM/128), 256>>>(p_hn, w1, b1, nullptr, p_f1, DDIM, FF);
    gemm_kernel<false,true><<<gp, 256>>>(p_f1, w2, b2, p_h, outp, FF, DDIM);

    u_row_kernel<<<MM, 128>>>(outp, x);
    u_mean_kernel<<<BB, 256>>>(outp, out_size);
}